// round 5
// baseline (speedup 1.0000x reference)
#include <cuda_runtime.h>

#define NPTS 4096
#define NCL  16
#define BLK  512

#define FMUL __fmul_rn
#define FADD __fadd_rn
#define FSUB __fsub_rn
#define FDIVR __fdiv_rn
#define FSQRT __fsqrt_rn

__device__ float4 g_nrm[NCL * NPTS];

__device__ __forceinline__ float sign_f(float a, float b) {
    float x = fabsf(a); return (b >= 0.f) ? x : -x;
}

__device__ __forceinline__ float slapy2f(float x, float y) {
    float xa = fabsf(x), ya = fabsf(y);
    float w = fmaxf(xa, ya), z = fminf(xa, ya);
    if (z == 0.f) return w;
    float t = FDIVR(z, w);
    return FMUL(w, FSQRT(FADD(1.f, FMUL(t, t))));
}

// LAPACK >= 3.10 slartg (moderate-range path)
__device__ __forceinline__ void slartg(float f, float g, float &c, float &s, float &r) {
    if (g == 0.f) { c = 1.f; s = 0.f; r = f; }
    else if (f == 0.f) { c = 0.f; s = (g >= 0.f) ? 1.f : -1.f; r = fabsf(g); }
    else {
        float d = FSQRT(FADD(FMUL(f, f), FMUL(g, g)));
        c = FDIVR(fabsf(f), d);
        r = sign_f(d, f);
        s = FDIVR(g, r);
    }
}

__device__ void slaev2(float a, float b, float cc,
                       float &rt1, float &rt2, float &cs1, float &sn1) {
    float sm = FADD(a, cc), df = FSUB(a, cc);
    float adf = fabsf(df), tb = FADD(b, b), ab = fabsf(tb);
    float acmx, acmn;
    if (fabsf(a) > fabsf(cc)) { acmx = a; acmn = cc; } else { acmx = cc; acmn = a; }
    float rt;
    if (adf > ab)      { float t = FDIVR(ab, adf); rt = FMUL(adf, FSQRT(FADD(1.f, FMUL(t, t)))); }
    else if (adf < ab) { float t = FDIVR(adf, ab); rt = FMUL(ab,  FSQRT(FADD(1.f, FMUL(t, t)))); }
    else               { rt = FMUL(ab, FSQRT(2.f)); }
    int sgn1;
    if (sm < 0.f) {
        rt1 = FMUL(0.5f, FSUB(sm, rt)); sgn1 = -1;
        rt2 = FSUB(FMUL(FDIVR(acmx, rt1), acmn), FMUL(FDIVR(b, rt1), b));
    } else if (sm > 0.f) {
        rt1 = FMUL(0.5f, FADD(sm, rt)); sgn1 = 1;
        rt2 = FSUB(FMUL(FDIVR(acmx, rt1), acmn), FMUL(FDIVR(b, rt1), b));
    } else { rt1 = FMUL(0.5f, rt); rt2 = FMUL(-0.5f, rt); sgn1 = 1; }
    float cs; int sgn2;
    if (df >= 0.f) { cs = FADD(df, rt); sgn2 = 1; }
    else           { cs = FSUB(df, rt); sgn2 = -1; }
    float acs = fabsf(cs);
    if (acs > ab) {
        float ct = FDIVR(-tb, cs);
        sn1 = FDIVR(1.f, FSQRT(FADD(1.f, FMUL(ct, ct))));
        cs1 = FMUL(ct, sn1);
    } else {
        if (ab == 0.f) { cs1 = 1.f; sn1 = 0.f; }
        else {
            float tn = FDIVR(-cs, tb);
            cs1 = FDIVR(1.f, FSQRT(FADD(1.f, FMUL(tn, tn))));
            sn1 = FMUL(tn, cs1);
        }
    }
    if (sgn1 == sgn2) { float t = cs1; cs1 = -sn1; sn1 = t; }
}

// SLASR inner rotation: right col cr, left col cl, stored (ct, st)
__device__ __forceinline__ void zrot(float z[3][3], int cl, int cr, float ct, float st) {
#pragma unroll
    for (int i = 0; i < 3; i++) {
        float t = z[i][cr];
        z[i][cr] = FSUB(FMUL(ct, t), FMUL(st, z[i][cl]));
        z[i][cl] = FADD(FMUL(st, t), FMUL(ct, z[i][cl]));
    }
}

// ssteqr, n=3, COMPZ='I' — direct netlib transcription
__device__ void ssteqr3(float *d, float *e, float z[3][3]) {
    const float eps = 5.9604645e-8f, eps2 = 3.5527137e-15f;
    const float safmin = 1.1754944e-38f;
    const float ssfmax = 3.0744574e18f, ssfmin = 3.0517578e-5f;
    const int n = 3, nmaxit = 90;
    int jtot = 0, l1 = 1, l = 0, lsv = 0, lend = 0, lendsv = 0, m = 0, iscale = 0;
    int mm, i, j, k, ii;
    float anorm = 0.f, p, g, r, c, s, f, b, rt1, rt2, tst, mul, pp, t;
    float cw[2], sw[2];
L10:
    if (l1 > n) goto L160;
    if (l1 > 1) e[l1 - 2] = 0.f;
    if (l1 <= n - 1) {
        for (m = l1; m <= n - 1; m++) {
            tst = fabsf(e[m - 1]);
            if (tst == 0.f) goto L30;
            if (tst <= FMUL(FMUL(FSQRT(fabsf(d[m - 1])), FSQRT(fabsf(d[m]))), eps)) {
                e[m - 1] = 0.f; goto L30;
            }
        }
    }
    m = n;
L30:
    l = l1; lsv = l; lend = m; lendsv = lend; l1 = m + 1;
    if (lend == l) goto L10;
    anorm = 0.f;
    for (i = l; i <= lend; i++) anorm = fmaxf(anorm, fabsf(d[i - 1]));
    for (i = l; i <  lend; i++) anorm = fmaxf(anorm, fabsf(e[i - 1]));
    iscale = 0;
    if (anorm == 0.f) goto L10;
    if (anorm > ssfmax) {
        iscale = 1; mul = FDIVR(ssfmax, anorm);
        for (i = l; i <= lend; i++) d[i - 1] = FMUL(d[i - 1], mul);
        for (i = l; i <  lend; i++) e[i - 1] = FMUL(e[i - 1], mul);
    } else if (anorm < ssfmin) {
        iscale = 2; mul = FDIVR(ssfmin, anorm);
        for (i = l; i <= lend; i++) d[i - 1] = FMUL(d[i - 1], mul);
        for (i = l; i <  lend; i++) e[i - 1] = FMUL(e[i - 1], mul);
    }
    if (fabsf(d[lend - 1]) < fabsf(d[l - 1])) { lend = lsv; l = lendsv; }
    if (lend > l) {
        // ---- QL ----
L40:
        if (l != lend) {
            for (m = l; m <= lend - 1; m++) {
                tst = FMUL(e[m - 1], e[m - 1]);
                if (tst <= FADD(FMUL(FMUL(eps2, fabsf(d[m - 1])), fabsf(d[m])), safmin)) goto L60;
            }
        }
        m = lend;
L60:
        if (m < lend) e[m - 1] = 0.f;
        p = d[l - 1];
        if (m == l) goto L80;
        if (m == l + 1) {
            slaev2(d[l - 1], e[l - 1], d[l], rt1, rt2, c, s);
            zrot(z, l - 1, l, c, s);     // netlib stores +S in the 2x2 case
            d[l - 1] = rt1; d[l] = rt2; e[l - 1] = 0.f;
            l += 2;
            if (l <= lend) goto L40;
            goto L140;
        }
        if (jtot == nmaxit) goto L140;
        jtot++;
        g = FDIVR(FSUB(d[l], p), FMUL(2.f, e[l - 1]));
        r = slapy2f(g, 1.f);
        g = FADD(FSUB(d[m - 1], p), FDIVR(e[l - 1], FADD(g, sign_f(r, g))));
        s = 1.f; c = 1.f; p = 0.f;
        for (i = m - 1; i >= l; i--) {
            f = FMUL(s, e[i - 1]); b = FMUL(c, e[i - 1]);
            slartg(g, f, c, s, r);
            if (i != m - 1) e[i] = r;
            g = FSUB(d[i], p);
            r = FADD(FMUL(FSUB(d[i - 1], g), s), FMUL(FMUL(2.f, c), b));
            p = FMUL(s, r);
            d[i] = FADD(g, p);
            g = FSUB(FMUL(c, r), b);
            cw[i - l] = c; sw[i - l] = -s;   // iteration loop stores -S
        }
        mm = m - l + 1;
        for (j = mm - 1; j >= 1; j--)
            if (cw[j - 1] != 1.f || sw[j - 1] != 0.f)
                zrot(z, l + j - 2, l + j - 1, cw[j - 1], sw[j - 1]);
        d[l - 1] = FSUB(d[l - 1], p);
        e[l - 1] = g;
        goto L40;
L80:
        d[l - 1] = p; l++;
        if (l <= lend) goto L40;
        goto L140;
    } else {
        // ---- QR ----
L90:
        if (l != lend) {
            for (m = l; m >= lend + 1; m--) {
                tst = FMUL(e[m - 2], e[m - 2]);
                if (tst <= FADD(FMUL(FMUL(eps2, fabsf(d[m - 1])), fabsf(d[m - 2])), safmin)) goto L110;
            }
        }
        m = lend;
L110:
        if (m > lend) e[m - 2] = 0.f;
        p = d[l - 1];
        if (m == l) goto L130;
        if (m == l - 1) {
            slaev2(d[l - 2], e[l - 2], d[l - 1], rt1, rt2, c, s);
            zrot(z, l - 2, l - 1, c, s);     // +S here too
            d[l - 2] = rt1; d[l - 1] = rt2; e[l - 2] = 0.f;
            l -= 2;
            if (l >= lend) goto L90;
            goto L140;
        }
        if (jtot == nmaxit) goto L140;
        jtot++;
        g = FDIVR(FSUB(d[l - 2], p), FMUL(2.f, e[l - 2]));
        r = slapy2f(g, 1.f);
        g = FADD(FSUB(d[m - 1], p), FDIVR(e[l - 2], FADD(g, sign_f(r, g))));
        s = 1.f; c = 1.f; p = 0.f;
        for (i = m; i <= l - 1; i++) {
            f = FMUL(s, e[i - 1]); b = FMUL(c, e[i - 1]);
            slartg(g, f, c, s, r);
            if (i != m) e[i - 2] = r;
            g = FSUB(d[i - 1], p);
            r = FADD(FMUL(FSUB(d[i], g), s), FMUL(FMUL(2.f, c), b));
            p = FMUL(s, r);
            d[i - 1] = FADD(g, p);
            g = FSUB(FMUL(c, r), b);
            cw[i - m] = c; sw[i - m] = s;    // QR iteration stores +S
        }
        mm = l - m + 1;
        for (j = 1; j <= mm - 1; j++)
            if (cw[j - 1] != 1.f || sw[j - 1] != 0.f)
                zrot(z, m + j - 2, m + j - 1, cw[j - 1], sw[j - 1]);
        d[l - 1] = FSUB(d[l - 1], p);
        e[l - 2] = g;
        goto L90;
L130:
        d[l - 1] = p; l--;
        if (l >= lend) goto L90;
        goto L140;
    }
L140:
    if (iscale == 1) {
        mul = FDIVR(anorm, ssfmax);
        for (i = lsv; i <= lendsv; i++) d[i - 1] = FMUL(d[i - 1], mul);
        for (i = lsv; i <  lendsv; i++) e[i - 1] = FMUL(e[i - 1], mul);
    } else if (iscale == 2) {
        mul = FDIVR(anorm, ssfmin);
        for (i = lsv; i <= lendsv; i++) d[i - 1] = FMUL(d[i - 1], mul);
        for (i = lsv; i <  lendsv; i++) e[i - 1] = FMUL(e[i - 1], mul);
    }
    if (jtot < nmaxit) goto L10;
L160:
    for (ii = 2; ii <= n; ii++) {
        i = ii - 1; k = i; pp = d[i - 1];
        for (j = ii; j <= n; j++)
            if (d[j - 1] < pp) { k = j; pp = d[j - 1]; }
        if (k != i) {
            d[k - 1] = d[i - 1]; d[i - 1] = pp;
#pragma unroll
            for (j = 0; j < 3; j++) { t = z[j][i - 1]; z[j][i - 1] = z[j][k - 1]; z[j][k - 1] = t; }
        }
    }
}

// ssyevd('V','L') 3x3: ssytd2 + ssteqr('I') + sormtr; return column 0
__device__ void eig3_smallest(float a00, float a10, float a20,
                              float a11, float a21, float a22,
                              float &nx, float &ny, float &nz) {
    float tau, v2, beta, alpha = a10, xnorm = fabsf(a20);
    float d[3], e[2];
    if (xnorm == 0.f) { tau = 0.f; v2 = 0.f; beta = alpha; }
    else {
        beta = -sign_f(slapy2f(alpha, xnorm), alpha);
        tau = FDIVR(FSUB(beta, alpha), beta);
        v2 = FMUL(a20, FDIVR(1.f, FSUB(alpha, beta)));
    }
    d[0] = a00; e[0] = beta;
    if (tau != 0.f) {
        float p0 = FADD(FMUL(tau, a11), FMUL(tau, FMUL(a21, v2)));
        float p1 = FADD(FMUL(tau, a21), FMUL(FMUL(tau, v2), a22));
        float dv = FADD(p0, FMUL(p1, v2));
        float al = FMUL(FMUL(-0.5f, tau), dv);
        float w0 = FADD(p0, al);
        float w1 = FADD(p1, FMUL(al, v2));
        d[1] = FSUB(FSUB(a11, w0), w0);
        e[1] = FSUB(FSUB(a21, FMUL(v2, w0)), w1);
        d[2] = FSUB(FSUB(a22, FMUL(v2, w1)), FMUL(w1, v2));
    } else { d[1] = a11; e[1] = a21; d[2] = a22; }
    float z[3][3] = {{1.f,0.f,0.f},{0.f,1.f,0.f},{0.f,0.f,1.f}};
    ssteqr3(d, e, z);
    float z0 = z[0][0], z1 = z[1][0], z2 = z[2][0];
    if (tau != 0.f) {                 // sormtr: apply H1
        float w = FADD(z1, FMUL(v2, z2));
        z1 = FSUB(z1, FMUL(tau, w));
        z2 = FSUB(z2, FMUL(FMUL(tau, v2), w));
    }
    nx = z0; ny = z1; nz = z2;
}

// ---------------------------------------------------------------------------
// Kernel A: per-point 10-NN + covariance + smallest-eigvec normal
// ---------------------------------------------------------------------------
__global__ __launch_bounds__(BLK)
void knn_normal_kernel(const float *__restrict__ pred, const float *__restrict__ gt) {
    extern __shared__ float4 sp[];
    int cloud = blockIdx.y;
    const float *base = (cloud < 8) ? pred + (size_t)cloud * 3 * NPTS
                                    : gt + (size_t)(cloud - 8) * 3 * NPTS;
    for (int i = threadIdx.x; i < NPTS; i += BLK) {
        float x = base[i], y = base[NPTS + i], zz = base[2 * NPTS + i];
        float sq = FADD(FADD(FMUL(x, x), FMUL(y, y)), FMUL(zz, zz));
        sp[i] = make_float4(x, y, zz, sq);
    }
    __syncthreads();

    int q = blockIdx.x * BLK + threadIdx.x;
    float4 me = sp[q];
    float nd[10]; int ni[10];
#pragma unroll
    for (int j = 0; j < 10; j++) { nd[j] = 3.4e38f; ni[j] = 0; }

    for (int m = 0; m < NPTS; m++) {
        float4 cc = sp[m];
        float dot = fmaf(me.z, cc.z, fmaf(me.y, cc.y, me.x * cc.x));
        float d2 = fmaf(-2.f, dot, FADD(me.w, cc.w));
        if (d2 < nd[9]) {           // strict: stable tie-break == jax top_k
            nd[9] = d2; ni[9] = m;
#pragma unroll
            for (int j = 9; j > 0; j--) {
                if (nd[j] < nd[j - 1]) {
                    float td = nd[j]; nd[j] = nd[j - 1]; nd[j - 1] = td;
                    int ti = ni[j]; ni[j] = ni[j - 1]; ni[j - 1] = ti;
                }
            }
        }
    }

    float sx = 0.f, sy = 0.f, sz = 0.f;
#pragma unroll
    for (int j = 0; j < 10; j++) {
        float4 cc = sp[ni[j]];
        sx = FADD(sx, cc.x); sy = FADD(sy, cc.y); sz = FADD(sz, cc.z);
    }
    float mx = FDIVR(sx, 10.f), my = FDIVR(sy, 10.f), mz = FDIVR(sz, 10.f);
    float cxx = 0.f, cxy = 0.f, cxz = 0.f, cyy = 0.f, cyz = 0.f, czz = 0.f;
#pragma unroll
    for (int j = 0; j < 10; j++) {
        float4 cc = sp[ni[j]];
        float ax = FSUB(cc.x, mx), ay = FSUB(cc.y, my), az = FSUB(cc.z, mz);
        cxx = fmaf(ax, ax, cxx); cxy = fmaf(ax, ay, cxy); cxz = fmaf(ax, az, cxz);
        cyy = fmaf(ay, ay, cyy); cyz = fmaf(ay, az, cyz); czz = fmaf(az, az, czz);
    }
    float nx, ny, nz;
    eig3_smallest(FDIVR(cxx, 10.f), FDIVR(cxy, 10.f), FDIVR(cxz, 10.f),
                  FDIVR(cyy, 10.f), FDIVR(cyz, 10.f), FDIVR(czz, 10.f),
                  nx, ny, nz);
    g_nrm[cloud * NPTS + q] = make_float4(nx, ny, nz, 0.f);
}

// ---------------------------------------------------------------------------
// Kernel B: loss = mean((pred_n - gt_n)^2)
// ---------------------------------------------------------------------------
__global__ void loss_kernel(float *__restrict__ out) {
    __shared__ double wsum[32];
    double acc = 0.0;
    for (int i = threadIdx.x; i < 8 * NPTS; i += 1024) {
        int b = i >> 12, n = i & (NPTS - 1);
        float4 p = g_nrm[b * NPTS + n];
        float4 g = g_nrm[(8 + b) * NPTS + n];
        float dx = p.x - g.x, dy = p.y - g.y, dz = p.z - g.z;
        acc += (double)dx * dx + (double)dy * dy + (double)dz * dz;
    }
    for (int o = 16; o > 0; o >>= 1) acc += __shfl_down_sync(0xffffffffu, acc, o);
    if ((threadIdx.x & 31) == 0) wsum[threadIdx.x >> 5] = acc;
    __syncthreads();
    if (threadIdx.x < 32) {
        double v = wsum[threadIdx.x];
        for (int o = 16; o > 0; o >>= 1) v += __shfl_down_sync(0xffffffffu, v, o);
        if (threadIdx.x == 0) out[0] = (float)(v / 98304.0);
    }
}

extern "C" void kernel_launch(void *const *d_in, const int *in_sizes, int n_in,
                              void *d_out, int out_size) {
    const float *pred = (const float *)d_in[0];
    const float *gt = (const float *)d_in[1];
    cudaFuncSetAttribute((const void *)knn_normal_kernel,
                         cudaFuncAttributeMaxDynamicSharedMemorySize, NPTS * sizeof(float4));
    dim3 grid(NPTS / BLK, NCL);
    knn_normal_kernel<<<grid, BLK, NPTS * sizeof(float4)>>>(pred, gt);
    loss_kernel<<<1, 1024>>>((float *)d_out);
}

// round 7
// speedup vs baseline: 1.2638x; 1.2638x over previous
#include <cuda_runtime.h>

#define NPTS 4096
#define NCL  16
#define BLK  256

#define FMUL __fmul_rn
#define FADD __fadd_rn
#define FSUB __fsub_rn
#define FDIVR __fdiv_rn
#define FSQRT __fsqrt_rn

__device__ float4 g_nrm[NCL * NPTS];
__device__ float4 g_cov_a[NCL * NPTS];   // cxx, cxy, cxz, cyy
__device__ float2 g_cov_b[NCL * NPTS];   // cyz, czz
__device__ double g_part[8];

__device__ __forceinline__ float sign_f(float a, float b) {
    float x = fabsf(a); return (b >= 0.f) ? x : -x;
}

__device__ __forceinline__ float slapy2f(float x, float y) {
    float xa = fabsf(x), ya = fabsf(y);
    float w = fmaxf(xa, ya), z = fminf(xa, ya);
    if (z == 0.f) return w;
    float t = FDIVR(z, w);
    return FMUL(w, FSQRT(FADD(1.f, FMUL(t, t))));
}

// LAPACK >= 3.10 slartg (moderate-range path)
__device__ __forceinline__ void slartg(float f, float g, float &c, float &s, float &r) {
    if (g == 0.f) { c = 1.f; s = 0.f; r = f; }
    else if (f == 0.f) { c = 0.f; s = (g >= 0.f) ? 1.f : -1.f; r = fabsf(g); }
    else {
        float d = FSQRT(FADD(FMUL(f, f), FMUL(g, g)));
        c = FDIVR(fabsf(f), d);
        r = sign_f(d, f);
        s = FDIVR(g, r);
    }
}

__device__ void slaev2(float a, float b, float cc,
                       float &rt1, float &rt2, float &cs1, float &sn1) {
    float sm = FADD(a, cc), df = FSUB(a, cc);
    float adf = fabsf(df), tb = FADD(b, b), ab = fabsf(tb);
    float acmx, acmn;
    if (fabsf(a) > fabsf(cc)) { acmx = a; acmn = cc; } else { acmx = cc; acmn = a; }
    float rt;
    if (adf > ab)      { float t = FDIVR(ab, adf); rt = FMUL(adf, FSQRT(FADD(1.f, FMUL(t, t)))); }
    else if (adf < ab) { float t = FDIVR(adf, ab); rt = FMUL(ab,  FSQRT(FADD(1.f, FMUL(t, t)))); }
    else               { rt = FMUL(ab, FSQRT(2.f)); }
    int sgn1;
    if (sm < 0.f) {
        rt1 = FMUL(0.5f, FSUB(sm, rt)); sgn1 = -1;
        rt2 = FSUB(FMUL(FDIVR(acmx, rt1), acmn), FMUL(FDIVR(b, rt1), b));
    } else if (sm > 0.f) {
        rt1 = FMUL(0.5f, FADD(sm, rt)); sgn1 = 1;
        rt2 = FSUB(FMUL(FDIVR(acmx, rt1), acmn), FMUL(FDIVR(b, rt1), b));
    } else { rt1 = FMUL(0.5f, rt); rt2 = FMUL(-0.5f, rt); sgn1 = 1; }
    float cs; int sgn2;
    if (df >= 0.f) { cs = FADD(df, rt); sgn2 = 1; }
    else           { cs = FSUB(df, rt); sgn2 = -1; }
    float acs = fabsf(cs);
    if (acs > ab) {
        float ct = FDIVR(-tb, cs);
        sn1 = FDIVR(1.f, FSQRT(FADD(1.f, FMUL(ct, ct))));
        cs1 = FMUL(ct, sn1);
    } else {
        if (ab == 0.f) { cs1 = 1.f; sn1 = 0.f; }
        else {
            float tn = FDIVR(-cs, tb);
            cs1 = FDIVR(1.f, FSQRT(FADD(1.f, FMUL(tn, tn))));
            sn1 = FMUL(tn, cs1);
        }
    }
    if (sgn1 == sgn2) { float t = cs1; cs1 = -sn1; sn1 = t; }
}

__device__ __forceinline__ void zrot(float z[3][3], int cl, int cr, float ct, float st) {
#pragma unroll
    for (int i = 0; i < 3; i++) {
        float t = z[i][cr];
        z[i][cr] = FSUB(FMUL(ct, t), FMUL(st, z[i][cl]));
        z[i][cl] = FADD(FMUL(st, t), FMUL(ct, z[i][cl]));
    }
}

// ssteqr, n=3, COMPZ='I' — netlib transcription
__device__ void ssteqr3(float *d, float *e, float z[3][3]) {
    const float eps = 5.9604645e-8f, eps2 = 3.5527137e-15f;
    const float safmin = 1.1754944e-38f;
    const float ssfmax = 3.0744574e18f, ssfmin = 3.0517578e-5f;
    const int n = 3, nmaxit = 90;
    int jtot = 0, l1 = 1, l = 0, lsv = 0, lend = 0, lendsv = 0, m = 0, iscale = 0;
    int mm, i, j, k, ii;
    float anorm = 0.f, p, g, r, c, s, f, b, rt1, rt2, tst, mul, pp, t;
    float cw[2], sw[2];
L10:
    if (l1 > n) goto L160;
    if (l1 > 1) e[l1 - 2] = 0.f;
    if (l1 <= n - 1) {
        for (m = l1; m <= n - 1; m++) {
            tst = fabsf(e[m - 1]);
            if (tst == 0.f) goto L30;
            if (tst <= FMUL(FMUL(FSQRT(fabsf(d[m - 1])), FSQRT(fabsf(d[m]))), eps)) {
                e[m - 1] = 0.f; goto L30;
            }
        }
    }
    m = n;
L30:
    l = l1; lsv = l; lend = m; lendsv = lend; l1 = m + 1;
    if (lend == l) goto L10;
    anorm = 0.f;
    for (i = l; i <= lend; i++) anorm = fmaxf(anorm, fabsf(d[i - 1]));
    for (i = l; i <  lend; i++) anorm = fmaxf(anorm, fabsf(e[i - 1]));
    iscale = 0;
    if (anorm == 0.f) goto L10;
    if (anorm > ssfmax) {
        iscale = 1; mul = FDIVR(ssfmax, anorm);
        for (i = l; i <= lend; i++) d[i - 1] = FMUL(d[i - 1], mul);
        for (i = l; i <  lend; i++) e[i - 1] = FMUL(e[i - 1], mul);
    } else if (anorm < ssfmin) {
        iscale = 2; mul = FDIVR(ssfmin, anorm);
        for (i = l; i <= lend; i++) d[i - 1] = FMUL(d[i - 1], mul);
        for (i = l; i <  lend; i++) e[i - 1] = FMUL(e[i - 1], mul);
    }
    if (fabsf(d[lend - 1]) < fabsf(d[l - 1])) { lend = lsv; l = lendsv; }
    if (lend > l) {
L40:
        if (l != lend) {
            for (m = l; m <= lend - 1; m++) {
                tst = FMUL(e[m - 1], e[m - 1]);
                if (tst <= FADD(FMUL(FMUL(eps2, fabsf(d[m - 1])), fabsf(d[m])), safmin)) goto L60;
            }
        }
        m = lend;
L60:
        if (m < lend) e[m - 1] = 0.f;
        p = d[l - 1];
        if (m == l) goto L80;
        if (m == l + 1) {
            slaev2(d[l - 1], e[l - 1], d[l], rt1, rt2, c, s);
            zrot(z, l - 1, l, c, s);
            d[l - 1] = rt1; d[l] = rt2; e[l - 1] = 0.f;
            l += 2;
            if (l <= lend) goto L40;
            goto L140;
        }
        if (jtot == nmaxit) goto L140;
        jtot++;
        g = FDIVR(FSUB(d[l], p), FMUL(2.f, e[l - 1]));
        r = slapy2f(g, 1.f);
        g = FADD(FSUB(d[m - 1], p), FDIVR(e[l - 1], FADD(g, sign_f(r, g))));
        s = 1.f; c = 1.f; p = 0.f;
        for (i = m - 1; i >= l; i--) {
            f = FMUL(s, e[i - 1]); b = FMUL(c, e[i - 1]);
            slartg(g, f, c, s, r);
            if (i != m - 1) e[i] = r;
            g = FSUB(d[i], p);
            r = FADD(FMUL(FSUB(d[i - 1], g), s), FMUL(FMUL(2.f, c), b));
            p = FMUL(s, r);
            d[i] = FADD(g, p);
            g = FSUB(FMUL(c, r), b);
            cw[i - l] = c; sw[i - l] = -s;
        }
        mm = m - l + 1;
        for (j = mm - 1; j >= 1; j--)
            if (cw[j - 1] != 1.f || sw[j - 1] != 0.f)
                zrot(z, l + j - 2, l + j - 1, cw[j - 1], sw[j - 1]);
        d[l - 1] = FSUB(d[l - 1], p);
        e[l - 1] = g;
        goto L40;
L80:
        d[l - 1] = p; l++;
        if (l <= lend) goto L40;
        goto L140;
    } else {
L90:
        if (l != lend) {
            for (m = l; m >= lend + 1; m--) {
                tst = FMUL(e[m - 2], e[m - 2]);
                if (tst <= FADD(FMUL(FMUL(eps2, fabsf(d[m - 1])), fabsf(d[m - 2])), safmin)) goto L110;
            }
        }
        m = lend;
L110:
        if (m > lend) e[m - 2] = 0.f;
        p = d[l - 1];
        if (m == l) goto L130;
        if (m == l - 1) {
            slaev2(d[l - 2], e[l - 2], d[l - 1], rt1, rt2, c, s);
            zrot(z, l - 2, l - 1, c, s);
            d[l - 2] = rt1; d[l - 1] = rt2; e[l - 2] = 0.f;
            l -= 2;
            if (l >= lend) goto L90;
            goto L140;
        }
        if (jtot == nmaxit) goto L140;
        jtot++;
        g = FDIVR(FSUB(d[l - 2], p), FMUL(2.f, e[l - 2]));
        r = slapy2f(g, 1.f);
        g = FADD(FSUB(d[m - 1], p), FDIVR(e[l - 2], FADD(g, sign_f(r, g))));
        s = 1.f; c = 1.f; p = 0.f;
        for (i = m; i <= l - 1; i++) {
            f = FMUL(s, e[i - 1]); b = FMUL(c, e[i - 1]);
            slartg(g, f, c, s, r);
            if (i != m) e[i - 2] = r;
            g = FSUB(d[i - 1], p);
            r = FADD(FMUL(FSUB(d[i], g), s), FMUL(FMUL(2.f, c), b));
            p = FMUL(s, r);
            d[i - 1] = FADD(g, p);
            g = FSUB(FMUL(c, r), b);
            cw[i - m] = c; sw[i - m] = s;
        }
        mm = l - m + 1;
        for (j = 1; j <= mm - 1; j++)
            if (cw[j - 1] != 1.f || sw[j - 1] != 0.f)
                zrot(z, m + j - 2, m + j - 1, cw[j - 1], sw[j - 1]);
        d[l - 1] = FSUB(d[l - 1], p);
        e[l - 2] = g;
        goto L90;
L130:
        d[l - 1] = p; l--;
        if (l >= lend) goto L90;
        goto L140;
    }
L140:
    if (iscale == 1) {
        mul = FDIVR(anorm, ssfmax);
        for (i = lsv; i <= lendsv; i++) d[i - 1] = FMUL(d[i - 1], mul);
        for (i = lsv; i <  lendsv; i++) e[i - 1] = FMUL(e[i - 1], mul);
    } else if (iscale == 2) {
        mul = FDIVR(anorm, ssfmin);
        for (i = lsv; i <= lendsv; i++) d[i - 1] = FMUL(d[i - 1], mul);
        for (i = lsv; i <  lendsv; i++) e[i - 1] = FMUL(e[i - 1], mul);
    }
    if (jtot < nmaxit) goto L10;
L160:
    for (ii = 2; ii <= n; ii++) {
        i = ii - 1; k = i; pp = d[i - 1];
        for (j = ii; j <= n; j++)
            if (d[j - 1] < pp) { k = j; pp = d[j - 1]; }
        if (k != i) {
            d[k - 1] = d[i - 1]; d[i - 1] = pp;
#pragma unroll
            for (j = 0; j < 3; j++) { t = z[j][i - 1]; z[j][i - 1] = z[j][k - 1]; z[j][k - 1] = t; }
        }
    }
}

__device__ void eig3_smallest(float a00, float a10, float a20,
                              float a11, float a21, float a22,
                              float &nx, float &ny, float &nz) {
    float tau, v2, beta, alpha = a10, xnorm = fabsf(a20);
    float d[3], e[2];
    if (xnorm == 0.f) { tau = 0.f; v2 = 0.f; beta = alpha; }
    else {
        beta = -sign_f(slapy2f(alpha, xnorm), alpha);
        tau = FDIVR(FSUB(beta, alpha), beta);
        v2 = FMUL(a20, FDIVR(1.f, FSUB(alpha, beta)));
    }
    d[0] = a00; e[0] = beta;
    if (tau != 0.f) {
        float p0 = FADD(FMUL(tau, a11), FMUL(tau, FMUL(a21, v2)));
        float p1 = FADD(FMUL(tau, a21), FMUL(FMUL(tau, v2), a22));
        float dv = FADD(p0, FMUL(p1, v2));
        float al = FMUL(FMUL(-0.5f, tau), dv);
        float w0 = FADD(p0, al);
        float w1 = FADD(p1, FMUL(al, v2));
        d[1] = FSUB(FSUB(a11, w0), w0);
        e[1] = FSUB(FSUB(a21, FMUL(v2, w0)), w1);
        d[2] = FSUB(FSUB(a22, FMUL(v2, w1)), FMUL(w1, v2));
    } else { d[1] = a11; e[1] = a21; d[2] = a22; }
    float z[3][3] = {{1.f,0.f,0.f},{0.f,1.f,0.f},{0.f,0.f,1.f}};
    ssteqr3(d, e, z);
    float z0 = z[0][0], z1 = z[1][0], z2 = z[2][0];
    if (tau != 0.f) {
        float w = FADD(z1, FMUL(v2, z2));
        z1 = FSUB(z1, FMUL(tau, w));
        z2 = FSUB(z2, FMUL(FMUL(tau, v2), w));
    }
    nx = z0; ny = z1; nz = z2;
}

// ---------------------------------------------------------------------------
// Kernel A: 10-NN scan + covariance (NO eig — keeps regs low, loop tight)
// grid (16 chunks, 16 clouds) x 256 threads, 64KB smem, 3 CTAs/SM
// ---------------------------------------------------------------------------
__global__ __launch_bounds__(BLK, 3)
void knn_cov_kernel(const float *__restrict__ pred, const float *__restrict__ gt) {
    extern __shared__ float4 sp[];
    int cloud = blockIdx.y;
    const float *base = (cloud < 8) ? pred + (size_t)cloud * 3 * NPTS
                                    : gt + (size_t)(cloud - 8) * 3 * NPTS;
    for (int i = threadIdx.x; i < NPTS; i += BLK) {
        float x = base[i], y = base[NPTS + i], zz = base[2 * NPTS + i];
        float sq = FADD(FADD(FMUL(x, x), FMUL(y, y)), FMUL(zz, zz));
        sp[i] = make_float4(x, y, zz, sq);
    }
    __syncthreads();

    int q = blockIdx.x * BLK + threadIdx.x;
    float4 me = sp[q];
    float nd[10]; int ni[10];
#pragma unroll
    for (int j = 0; j < 10; j++) { nd[j] = 3.4e38f; ni[j] = 0; }

#pragma unroll 8
    for (int m = 0; m < NPTS; m++) {
        float4 cc = sp[m];
        float dot = fmaf(me.z, cc.z, fmaf(me.y, cc.y, me.x * cc.x));
        float d2 = fmaf(-2.f, dot, FADD(me.w, cc.w));
        if (d2 < nd[9]) {           // strict: stable tie-break == jax top_k
            nd[9] = d2; ni[9] = m;
#pragma unroll
            for (int j = 9; j > 0; j--) {
                if (nd[j] < nd[j - 1]) {
                    float td = nd[j]; nd[j] = nd[j - 1]; nd[j - 1] = td;
                    int ti = ni[j]; ni[j] = ni[j - 1]; ni[j - 1] = ti;
                }
            }
        }
    }

    float sx = 0.f, sy = 0.f, sz = 0.f;
#pragma unroll
    for (int j = 0; j < 10; j++) {
        float4 cc = sp[ni[j]];
        sx = FADD(sx, cc.x); sy = FADD(sy, cc.y); sz = FADD(sz, cc.z);
    }
    float mx = FDIVR(sx, 10.f), my = FDIVR(sy, 10.f), mz = FDIVR(sz, 10.f);
    float cxx = 0.f, cxy = 0.f, cxz = 0.f, cyy = 0.f, cyz = 0.f, czz = 0.f;
#pragma unroll
    for (int j = 0; j < 10; j++) {
        float4 cc = sp[ni[j]];
        float ax = FSUB(cc.x, mx), ay = FSUB(cc.y, my), az = FSUB(cc.z, mz);
        cxx = fmaf(ax, ax, cxx); cxy = fmaf(ax, ay, cxy); cxz = fmaf(ax, az, cxz);
        cyy = fmaf(ay, ay, cyy); cyz = fmaf(ay, az, cyz); czz = fmaf(az, az, czz);
    }
    int idx = cloud * NPTS + q;
    g_cov_a[idx] = make_float4(cxx, cxy, cxz, cyy);
    g_cov_b[idx] = make_float2(cyz, czz);
}

// ---------------------------------------------------------------------------
// Kernel B: per-point 3x3 eigh (LAPACK-faithful), heavy regs OK here
// ---------------------------------------------------------------------------
__global__ __launch_bounds__(256)
void eig_kernel() {
    int idx = blockIdx.x * 256 + threadIdx.x;
    float4 ca = g_cov_a[idx];
    float2 cb = g_cov_b[idx];
    float nx, ny, nz;
    eig3_smallest(FDIVR(ca.x, 10.f), FDIVR(ca.y, 10.f), FDIVR(ca.z, 10.f),
                  FDIVR(ca.w, 10.f), FDIVR(cb.x, 10.f), FDIVR(cb.y, 10.f),
                  nx, ny, nz);
    g_nrm[idx] = make_float4(nx, ny, nz, 0.f);
}

// ---------------------------------------------------------------------------
// Kernel C1: 8 partial sums (one CTA per batch, deterministic)
// ---------------------------------------------------------------------------
__global__ void loss_partial_kernel() {
    __shared__ double wsum[16];
    int b = blockIdx.x;
    double acc = 0.0;
    for (int n = threadIdx.x; n < NPTS; n += 512) {
        float4 p = g_nrm[b * NPTS + n];
        float4 g = g_nrm[(8 + b) * NPTS + n];
        float dx = p.x - g.x, dy = p.y - g.y, dz = p.z - g.z;
        acc += (double)dx * dx + (double)dy * dy + (double)dz * dz;
    }
    for (int o = 16; o > 0; o >>= 1) acc += __shfl_down_sync(0xffffffffu, acc, o);
    if ((threadIdx.x & 31) == 0) wsum[threadIdx.x >> 5] = acc;
    __syncthreads();
    if (threadIdx.x < 16) {
        double v = wsum[threadIdx.x];
        for (int o = 8; o > 0; o >>= 1) v += __shfl_down_sync(0xffffu, v, o);
        if (threadIdx.x == 0) g_part[b] = v;
    }
}

// Kernel C2: finalize
__global__ void loss_final_kernel(float *__restrict__ out) {
    if (threadIdx.x == 0) {
        double v = 0.0;
        for (int i = 0; i < 8; i++) v += g_part[i];
        out[0] = (float)(v / 98304.0);
    }
}

extern "C" void kernel_launch(void *const *d_in, const int *in_sizes, int n_in,
                              void *d_out, int out_size) {
    const float *pred = (const float *)d_in[0];
    const float *gt = (const float *)d_in[1];
    cudaFuncSetAttribute((const void *)knn_cov_kernel,
                         cudaFuncAttributeMaxDynamicSharedMemorySize, NPTS * sizeof(float4));
    dim3 grid(NPTS / BLK, NCL);
    knn_cov_kernel<<<grid, BLK, NPTS * sizeof(float4)>>>(pred, gt);
    eig_kernel<<<NCL * NPTS / 256, 256>>>();
    loss_partial_kernel<<<8, 512>>>();
    loss_final_kernel<<<1, 32>>>((float *)d_out);
}